// round 8
// baseline (speedup 1.0000x reference)
#include <cuda_runtime.h>
#include <cuda_bf16.h>

#define FULL 0xffffffffu

struct C2 { float x, y; };
__device__ __forceinline__ C2 mkc(float x, float y){ C2 c; c.x=x; c.y=y; return c; }
#define DUP(s) mkc((s),(s))

// ---------- packed f32x2 elementwise ops (FFMA2 path, sm_100+) ----------
__device__ __forceinline__ C2 pfma(C2 a, C2 b, C2 c){  // per-component a*b+c
    C2 r;
    asm("{\n\t.reg .b64 A,B,C,D;\n\t"
        "mov.b64 A,{%2,%3};\n\t"
        "mov.b64 B,{%4,%5};\n\t"
        "mov.b64 C,{%6,%7};\n\t"
        "fma.rn.f32x2 D, A, B, C;\n\t"
        "mov.b64 {%0,%1}, D;\n\t}"
        : "=f"(r.x), "=f"(r.y)
        : "f"(a.x), "f"(a.y), "f"(b.x), "f"(b.y), "f"(c.x), "f"(c.y));
    return r;
}
__device__ __forceinline__ C2 pmul(C2 a, C2 b){        // per-component a*b
    C2 r;
    asm("{\n\t.reg .b64 A,B,D;\n\t"
        "mov.b64 A,{%2,%3};\n\t"
        "mov.b64 B,{%4,%5};\n\t"
        "mul.rn.f32x2 D, A, B;\n\t"
        "mov.b64 {%0,%1}, D;\n\t}"
        : "=f"(r.x), "=f"(r.y)
        : "f"(a.x), "f"(a.y), "f"(b.x), "f"(b.y));
    return r;
}

// Mapping: 16 amplitudes/thread (k bits 0..3), 16 lanes/element (lane bits 0..3),
// element = lane bit 4 (2 elements per warp).
//   odd qubits  (1,3,5,7) -> LOCAL reg bits : q7->k1, q5->k2, q3->k4, q1->k8
//   even qubits (0,2,4,6) -> LANE bits      : q6->l1, q4->l2, q2->l4, q0->l8
template<int Q> struct QM {
    static constexpr bool local = (Q & 1) != 0;
    static constexpr int mask = local ? (1 << ((7 - Q) >> 1)) : (1 << ((6 - Q) >> 1));
};

// ---------------- generic complex 1q gate (packed) ----------------
template<int Q>
__device__ __forceinline__ void g1(C2 a[16], C2 u00, C2 u01, C2 u10, C2 u11, int lane){
    constexpr int m = QM<Q>::mask;
    if constexpr (QM<Q>::local) {
        C2 x00 = DUP(u00.x), y00 = mkc(-u00.y, u00.y);
        C2 x01 = DUP(u01.x), y01 = mkc(-u01.y, u01.y);
        C2 x10 = DUP(u10.x), y10 = mkc(-u10.y, u10.y);
        C2 x11 = DUP(u11.x), y11 = mkc(-u11.y, u11.y);
        #pragma unroll
        for (int k0 = 0; k0 < 16; ++k0) if (!(k0 & m)) {
            int k1 = k0 | m;
            C2 a0 = a[k0], a1 = a[k1];
            C2 a0s = mkc(a0.y, a0.x), a1s = mkc(a1.y, a1.x);
            C2 t0 = pmul(x00, a0); t0 = pfma(y00, a0s, t0);
            t0 = pfma(x01, a1, t0); t0 = pfma(y01, a1s, t0);
            C2 t1 = pmul(x10, a0); t1 = pfma(y10, a0s, t1);
            t1 = pfma(x11, a1, t1); t1 = pfma(y11, a1s, t1);
            a[k0] = t0; a[k1] = t1;
        }
    } else {
        bool hi = (lane & m) != 0;
        C2 xA = hi ? DUP(u11.x) : DUP(u00.x);
        C2 yA = hi ? mkc(-u11.y, u11.y) : mkc(-u00.y, u00.y);
        C2 xB = hi ? DUP(u10.x) : DUP(u01.x);
        C2 yB = hi ? mkc(-u10.y, u10.y) : mkc(-u01.y, u01.y);
        #pragma unroll
        for (int k = 0; k < 16; ++k) {
            float px = __shfl_xor_sync(FULL, a[k].x, m);
            float py = __shfl_xor_sync(FULL, a[k].y, m);
            C2 as_ = mkc(a[k].y, a[k].x);
            C2 t = pmul(xA, a[k]); t = pfma(yA, as_, t);
            t = pfma(xB, mkc(px, py), t); t = pfma(yB, mkc(py, px), t);
            a[k] = t;
        }
    }
}

// ---------------- RY (packed) ----------------
template<int Q>
__device__ __forceinline__ void gry(C2 a[16], float c, float s, int lane){
    constexpr int m = QM<Q>::mask;
    C2 c2 = DUP(c);
    if constexpr (QM<Q>::local) {
        C2 s2 = DUP(s), ns2 = DUP(-s);
        #pragma unroll
        for (int k0 = 0; k0 < 16; ++k0) if (!(k0 & m)) {
            int k1 = k0 | m;
            C2 a0 = a[k0], a1 = a[k1];
            a[k0] = pfma(c2, a0, pmul(ns2, a1));
            a[k1] = pfma(s2, a0, pmul(c2, a1));
        }
    } else {
        C2 sg2 = (lane & m) ? DUP(s) : DUP(-s);
        #pragma unroll
        for (int k = 0; k < 16; ++k) {
            C2 p;
            p.x = __shfl_xor_sync(FULL, a[k].x, m);
            p.y = __shfl_xor_sync(FULL, a[k].y, m);
            a[k] = pfma(c2, a[k], pmul(sg2, p));
        }
    }
}

// ---------------- RZ up to global phase: diag(1, w) ----------------
template<int Q>
__device__ __forceinline__ void grzw(C2 a[16], C2 w, int lane){
    constexpr int m = QM<Q>::mask;
    C2 wx2 = DUP(w.x);
    C2 wy2 = mkc(-w.y, w.y);
    if constexpr (QM<Q>::local) {
        #pragma unroll
        for (int k = 0; k < 16; ++k) if (k & m)
            a[k] = pfma(wy2, mkc(a[k].y, a[k].x), pmul(wx2, a[k]));
    } else {
        C2 ex2 = (lane & m) ? wx2 : DUP(1.f);
        C2 ey2 = (lane & m) ? wy2 : DUP(0.f);
        #pragma unroll
        for (int k = 0; k < 16; ++k)
            a[k] = pfma(ey2, mkc(a[k].y, a[k].x), pmul(ex2, a[k]));
    }
}

// RZ(∓π/2) up to phase: diag(1, ∓i)
template<int Q, int SGN>
__device__ __forceinline__ void grz_i(C2 a[16], int lane){
    constexpr int m = QM<Q>::mask;
    if constexpr (QM<Q>::local) {
        #pragma unroll
        for (int k = 0; k < 16; ++k) if (k & m) {
            float t = a[k].x;
            if constexpr (SGN < 0) { a[k].x =  a[k].y; a[k].y = -t; }
            else                   { a[k].x = -a[k].y; a[k].y =  t; }
        }
    } else {
        bool hi = (lane & m) != 0;
        #pragma unroll
        for (int k = 0; k < 16; ++k) {
            float nx, ny;
            if constexpr (SGN < 0) { nx =  a[k].y; ny = -a[k].x; }
            else                   { nx = -a[k].y; ny =  a[k].x; }
            a[k].x = hi ? nx : a[k].x;
            a[k].y = hi ? ny : a[k].y;
        }
    }
}

// ---------------- CX ----------------
template<int QC, int QT>
__device__ __forceinline__ void gcx(C2 a[16], int lane){
    constexpr int mc = QM<QC>::mask, mt = QM<QT>::mask;
    if constexpr (QM<QC>::local && QM<QT>::local) {
        #pragma unroll
        for (int k0 = 0; k0 < 16; ++k0) if ((k0 & mc) && !(k0 & mt)) {
            int k1 = k0 | mt; C2 t = a[k0]; a[k0] = a[k1]; a[k1] = t;
        }
    } else if constexpr (QM<QC>::local) { // control local, target lane
        #pragma unroll
        for (int k = 0; k < 16; ++k) if (k & mc) {
            a[k].x = __shfl_xor_sync(FULL, a[k].x, mt);
            a[k].y = __shfl_xor_sync(FULL, a[k].y, mt);
        }
    } else if constexpr (QM<QT>::local) { // control lane, target local
        bool cb = (lane & mc) != 0;
        #pragma unroll
        for (int k0 = 0; k0 < 16; ++k0) if (!(k0 & mt)) {
            int k1 = k0 | mt;
            C2 t0 = a[k0], t1 = a[k1];
            a[k0] = cb ? t1 : t0;
            a[k1] = cb ? t0 : t1;
        }
    } else { // both lane (unused)
        bool cb = (lane & mc) != 0;
        #pragma unroll
        for (int k = 0; k < 16; ++k) {
            float px = __shfl_xor_sync(FULL, a[k].x, mt);
            float py = __shfl_xor_sync(FULL, a[k].y, mt);
            if (cb) { a[k].x = px; a[k].y = py; }
        }
    }
}

// ---------------- CRX (packed) ----------------
template<int QC, int QT>
__device__ __forceinline__ void gcrx(C2 a[16], float c, float s, int lane){
    constexpr int mc = QM<QC>::mask, mt = QM<QT>::mask;
    if constexpr (QM<QC>::local && QM<QT>::local) {
        C2 c2 = DUP(c), sn = mkc(s, -s);
        #pragma unroll
        for (int k0 = 0; k0 < 16; ++k0) if ((k0 & mc) && !(k0 & mt)) {
            int k1 = k0 | mt;
            C2 a0 = a[k0], a1 = a[k1];
            a[k0] = pfma(c2, a0, pmul(sn, mkc(a1.y, a1.x)));
            a[k1] = pfma(c2, a1, pmul(sn, mkc(a0.y, a0.x)));
        }
    } else if constexpr (QM<QC>::local) { // control local, target lane
        C2 c2 = DUP(c), sn = mkc(s, -s);
        #pragma unroll
        for (int k = 0; k < 16; ++k) if (k & mc) {
            float px = __shfl_xor_sync(FULL, a[k].x, mt);
            float py = __shfl_xor_sync(FULL, a[k].y, mt);
            a[k] = pfma(c2, a[k], pmul(sn, mkc(py, px)));
        }
    } else if constexpr (QM<QT>::local) { // control lane, target local
        bool cb = (lane & mc) != 0;
        C2 c2 = DUP(cb ? c : 1.0f);
        C2 sn = cb ? mkc(s, -s) : mkc(0.f, 0.f);
        #pragma unroll
        for (int k0 = 0; k0 < 16; ++k0) if (!(k0 & mt)) {
            int k1 = k0 | mt;
            C2 a0 = a[k0], a1 = a[k1];
            a[k0] = pfma(c2, a0, pmul(sn, mkc(a1.y, a1.x)));
            a[k1] = pfma(c2, a1, pmul(sn, mkc(a0.y, a0.x)));
        }
    } else { // both lane (unused)
        bool cb = (lane & mc) != 0;
        C2 c2 = DUP(cb ? c : 1.0f);
        C2 sn = cb ? mkc(s, -s) : mkc(0.f, 0.f);
        #pragma unroll
        for (int k = 0; k < 16; ++k) {
            float px = __shfl_xor_sync(FULL, a[k].x, mt);
            float py = __shfl_xor_sync(FULL, a[k].y, mt);
            a[k] = pfma(c2, a[k], pmul(sn, mkc(py, px)));
        }
    }
}

// ---------------- real-state encode gates ----------------
template<int Q>
__device__ __forceinline__ void gryR(float r[16], float c, float s, int lane){
    constexpr int m = QM<Q>::mask;
    C2 c2 = DUP(c);
    if constexpr (QM<Q>::local) {
        if constexpr (m == 1) {
            C2 snn = mkc(-s, s);
            #pragma unroll
            for (int j = 0; j < 8; ++j) {
                C2 v = mkc(r[2*j], r[2*j+1]);
                C2 res = pfma(snn, mkc(v.y, v.x), pmul(c2, v));
                r[2*j] = res.x; r[2*j+1] = res.y;
            }
        } else {
            constexpr int pm = m >> 1;
            C2 s2 = DUP(s), ns2 = DUP(-s);
            #pragma unroll
            for (int j0 = 0; j0 < 8; ++j0) if (!(j0 & pm)) {
                int j1 = j0 | pm;
                C2 v0 = mkc(r[2*j0], r[2*j0+1]);
                C2 v1 = mkc(r[2*j1], r[2*j1+1]);
                C2 n0 = pfma(c2, v0, pmul(ns2, v1));
                C2 n1 = pfma(s2, v0, pmul(c2, v1));
                r[2*j0] = n0.x; r[2*j0+1] = n0.y;
                r[2*j1] = n1.x; r[2*j1+1] = n1.y;
            }
        }
    } else {
        C2 sg2 = (lane & m) ? DUP(s) : DUP(-s);
        #pragma unroll
        for (int j = 0; j < 8; ++j) {
            float px = __shfl_xor_sync(FULL, r[2*j],   m);
            float py = __shfl_xor_sync(FULL, r[2*j+1], m);
            C2 v = mkc(r[2*j], r[2*j+1]);
            C2 res = pfma(c2, v, pmul(sg2, mkc(px, py)));
            r[2*j] = res.x; r[2*j+1] = res.y;
        }
    }
}

template<int QC, int QT>
__device__ __forceinline__ void gcxR(float r[16], int lane){
    constexpr int mc = QM<QC>::mask, mt = QM<QT>::mask;
    if constexpr (QM<QC>::local && QM<QT>::local) {
        #pragma unroll
        for (int k0 = 0; k0 < 16; ++k0) if ((k0 & mc) && !(k0 & mt)) {
            int k1 = k0 | mt; float t = r[k0]; r[k0] = r[k1]; r[k1] = t;
        }
    } else if constexpr (QM<QC>::local) {
        #pragma unroll
        for (int k = 0; k < 16; ++k) if (k & mc)
            r[k] = __shfl_xor_sync(FULL, r[k], mt);
    } else if constexpr (QM<QT>::local) {
        bool cb = (lane & mc) != 0;
        #pragma unroll
        for (int k0 = 0; k0 < 16; ++k0) if (!(k0 & mt)) {
            int k1 = k0 | mt;
            float t0 = r[k0], t1 = r[k1];
            r[k0] = cb ? t1 : t0;
            r[k1] = cb ? t0 : t1;
        }
    } else {
        bool cb = (lane & mc) != 0;
        #pragma unroll
        for (int k = 0; k < 16; ++k) {
            float pv = __shfl_xor_sync(FULL, r[k], mt);
            r[k] = cb ? pv : r[k];
        }
    }
}

// sum within each 16-lane half of the warp
__device__ __forceinline__ float wsum16(float v){
    #pragma unroll
    for (int o = 8; o; o >>= 1) v += __shfl_xor_sync(FULL, v, o);
    return v;
}

// U3 matrix from (theta, phi, lambda)
__device__ __forceinline__ void u3m(const float* p, C2& U00, C2& U01, C2& U10, C2& U11){
    float t = p[0], ph = p[1], la = p[2];
    float st, ct, sp, cp, sl, cl, spl, cpl;
    __sincosf(t * 0.5f, &st, &ct);
    __sincosf(ph, &sp, &cp);
    __sincosf(la, &sl, &cl);
    __sincosf(ph + la, &spl, &cpl);
    U00 = mkc(ct, 0.f);
    U01 = mkc(-cl*st, -sl*st);
    U10 = mkc( cp*st,  sp*st);
    U11 = mkc(cpl*ct, spl*ct);
}

__global__ void __launch_bounds__(128, 8)
qcnn_kernel(const float* __restrict__ x,
            const float* __restrict__ rz_p,  const float* __restrict__ ry_p,
            const float* __restrict__ ry2_p, const float* __restrict__ crx_p,
            const float* __restrict__ u3_p,  const float* __restrict__ u3b_p,
            const float* __restrict__ W1,    const float* __restrict__ b1,
            const float* __restrict__ W2,    const float* __restrict__ b2,
            float* __restrict__ out, int B)
{
    const int warp = (blockIdx.x * blockDim.x + threadIdx.x) >> 5;
    const int lane = threadIdx.x & 31;
    const int hl   = lane & 15;
    const int elem = warp * 2 + (lane >> 4);
    if (warp * 2 >= B) return;               // whole-warp uniform exit
    const int e = (elem < B) ? elem : (B - 1);

    // ================= encode (state purely REAL) =================
    float2 av = reinterpret_cast<const float2*>(x)[e * 16 + hl];
    float c0, s0, c1, s1;
    __sincosf(0.5f * av.x, &s0, &c0);
    __sincosf(0.5f * av.y, &s1, &c1);

    float r[16];
    #pragma unroll
    for (int k = 0; k < 16; ++k) r[k] = 0.0f;
    r[0] = (hl == 0) ? 1.0f : 0.0f;

    #define RYQ(CY,Q) do { \
        const int idx_ = (CY)*8 + (Q); \
        int src_ = (lane & 16) | (idx_ >> 1); \
        float cc_ = __shfl_sync(FULL, ((idx_ & 1) ? c1 : c0), src_); \
        float ss_ = __shfl_sync(FULL, ((idx_ & 1) ? s1 : s0), src_); \
        gryR<Q>(r, cc_, ss_, lane); } while(0)

    #define ENC_CYC(CY) \
        RYQ(CY,0); RYQ(CY,1); RYQ(CY,2); RYQ(CY,3); \
        RYQ(CY,4); RYQ(CY,5); RYQ(CY,6); RYQ(CY,7); \
        gcxR<0,1>(r,lane); gcxR<1,2>(r,lane); gcxR<2,3>(r,lane); gcxR<3,4>(r,lane); \
        gcxR<4,5>(r,lane); gcxR<5,6>(r,lane); gcxR<6,7>(r,lane); gcxR<7,0>(r,lane);

    ENC_CYC(0) ENC_CYC(1) ENC_CYC(2) ENC_CYC(3)

    // ================= psi1 FIRST (short circuit; r stays live only here) ====
    C2 a[16];
    #pragma unroll
    for (int k = 0; k < 16; ++k) a[k] = mkc(r[k], 0.f);

    {   // layer 0
        float xc, xs;
        __sincosf(crx_p[0] * 0.5f, &xs, &xc);
        gcrx<0,1>(a, xc, xs, lane);
        gcrx<2,3>(a, xc, xs, lane);
        gcrx<4,5>(a, xc, xs, lane);
        gcrx<6,7>(a, xc, xs, lane);
        gcrx<1,2>(a, xc, xs, lane);
        gcrx<3,4>(a, xc, xs, lane);
        gcrx<5,6>(a, xc, xs, lane);
        C2 U00, U01, U10, U11;
        u3m(u3b_p, U00, U01, U10, U11);
        g1<1>(a, U00, U01, U10, U11, lane);
        g1<3>(a, U00, U01, U10, U11, lane);
        g1<5>(a, U00, U01, U10, U11, lane);
        g1<7>(a, U00, U01, U10, U11, lane);
    }
    {   // layer 1
        float xc, xs;
        __sincosf(crx_p[1] * 0.5f, &xs, &xc);
        gcrx<1,3>(a, xc, xs, lane);
        gcrx<5,7>(a, xc, xs, lane);
        gcrx<3,5>(a, xc, xs, lane);
        C2 U00, U01, U10, U11;
        u3m(u3b_p + 3, U00, U01, U10, U11);
        g1<3>(a, U00, U01, U10, U11, lane);
        g1<7>(a, U00, U01, U10, U11, lane);
    }

    // measure psi1: qubit3 -> k bit2 (mask 4), qubit7 -> k bit0 (mask 1)
    float f2, f3;
    {
        float p3 = 0.f, p7 = 0.f;
        #pragma unroll
        for (int k = 0; k < 16; ++k) {
            float m = fmaf(a[k].x, a[k].x, a[k].y * a[k].y);
            p3 += (k & 4) ? -m : m;
            p7 += (k & 1) ? -m : m;
        }
        f2 = wsum16(p3);
        f3 = wsum16(p7);
    }

    // ================= psi0 (r dies right here) =================
    #pragma unroll
    for (int k = 0; k < 16; ++k) a[k] = mkc(r[k], 0.f);

    #define BLK(QC,QT,WZ,YC,YS,Y2C,Y2S) \
        grz_i<QT,-1>(a, lane); \
        gcx<QT,QC>(a, lane); \
        grzw<QC>(a, WZ, lane); \
        gry<QT>(a, YC, YS, lane); \
        gcx<QC,QT>(a, lane); \
        gry<QT>(a, Y2C, Y2S, lane); \
        gcx<QT,QC>(a, lane); \
        grz_i<QC,+1>(a, lane);

    {   // layer 0
        float zs, zc, yc, ys, y2c, y2s;
        __sincosf(rz_p[0], &zs, &zc);
        C2 wz = mkc(zc, zs);
        __sincosf(ry_p[0]  * 0.5f, &ys,  &yc);
        __sincosf(ry2_p[0] * 0.5f, &y2s, &y2c);
        BLK(0,1,wz,yc,ys,y2c,y2s) BLK(2,3,wz,yc,ys,y2c,y2s)
        BLK(4,5,wz,yc,ys,y2c,y2s) BLK(6,7,wz,yc,ys,y2c,y2s)
        BLK(1,2,wz,yc,ys,y2c,y2s) BLK(3,4,wz,yc,ys,y2c,y2s)
        BLK(5,6,wz,yc,ys,y2c,y2s)
        C2 U00, U01, U10, U11;
        u3m(u3_p, U00, U01, U10, U11);
        g1<1>(a, U00, U01, U10, U11, lane);
        g1<3>(a, U00, U01, U10, U11, lane);
        g1<5>(a, U00, U01, U10, U11, lane);
        g1<7>(a, U00, U01, U10, U11, lane);
    }
    {   // layer 1
        float zs, zc, yc, ys, y2c, y2s;
        __sincosf(rz_p[1], &zs, &zc);
        C2 wz = mkc(zc, zs);
        __sincosf(ry_p[1]  * 0.5f, &ys,  &yc);
        __sincosf(ry2_p[1] * 0.5f, &y2s, &y2c);
        BLK(1,3,wz,yc,ys,y2c,y2s) BLK(5,7,wz,yc,ys,y2c,y2s)
        BLK(3,5,wz,yc,ys,y2c,y2s)
        C2 U00, U01, U10, U11;
        u3m(u3_p + 3, U00, U01, U10, U11);
        g1<3>(a, U00, U01, U10, U11, lane);
        g1<7>(a, U00, U01, U10, U11, lane);
    }

    // measure psi0
    float f0, f1;
    {
        float p3 = 0.f, p7 = 0.f;
        #pragma unroll
        for (int k = 0; k < 16; ++k) {
            float m = fmaf(a[k].x, a[k].x, a[k].y * a[k].y);
            p3 += (k & 4) ? -m : m;
            p7 += (k & 1) ? -m : m;
        }
        f0 = wsum16(p3);
        f1 = wsum16(p7);
    }

    // ================= MLP head =================
    float hv = 0.f;
    if (hl < 15) {
        float z = b1[hl];
        z = fmaf(W1[hl*4+0], f0, z);
        z = fmaf(W1[hl*4+1], f1, z);
        z = fmaf(W1[hl*4+2], f2, z);
        z = fmaf(W1[hl*4+3], f3, z);
        hv = tanhf(z) * W2[hl];
    }
    float s = wsum16(hv);
    if (hl == 0 && elem < B) {
        float zf = s + b2[0];
        out[elem] = 1.0f / (1.0f + __expf(-zf));
    }
}

extern "C" void kernel_launch(void* const* d_in, const int* in_sizes, int n_in,
                              void* d_out, int out_size) {
    const float* x     = (const float*)d_in[0];
    const float* rz_p  = (const float*)d_in[1];
    const float* ry_p  = (const float*)d_in[2];
    const float* ry2_p = (const float*)d_in[3];
    const float* crx_p = (const float*)d_in[4];
    const float* u3_p  = (const float*)d_in[5];
    const float* u3b_p = (const float*)d_in[6];
    const float* W1    = (const float*)d_in[7];
    const float* b1    = (const float*)d_in[8];
    const float* W2    = (const float*)d_in[9];
    const float* b2    = (const float*)d_in[10];

    int B = in_sizes[0] / 32;          // x is (B, 32)
    const int threads = 128;           // 4 warps/block, 8 elements/block
    int blocks = (B + 7) / 8;
    qcnn_kernel<<<blocks, threads>>>(x, rz_p, ry_p, ry2_p, crx_p, u3_p, u3b_p,
                                     W1, b1, W2, b2, (float*)d_out, B);
}

// round 9
// speedup vs baseline: 1.1597x; 1.1597x over previous
#include <cuda_runtime.h>
#include <cuda_bf16.h>

#define FULL 0xffffffffu

struct C2 { float x, y; };
__device__ __forceinline__ C2 mkc(float x, float y){ C2 c; c.x=x; c.y=y; return c; }
#define DUP(s) mkc((s),(s))

// ---------- packed f32x2 elementwise ops ----------
__device__ __forceinline__ C2 pfma(C2 a, C2 b, C2 c){
    C2 r;
    asm("{\n\t.reg .b64 A,B,C,D;\n\t"
        "mov.b64 A,{%2,%3};\n\t"
        "mov.b64 B,{%4,%5};\n\t"
        "mov.b64 C,{%6,%7};\n\t"
        "fma.rn.f32x2 D, A, B, C;\n\t"
        "mov.b64 {%0,%1}, D;\n\t}"
        : "=f"(r.x), "=f"(r.y)
        : "f"(a.x), "f"(a.y), "f"(b.x), "f"(b.y), "f"(c.x), "f"(c.y));
    return r;
}
__device__ __forceinline__ C2 pmul(C2 a, C2 b){
    C2 r;
    asm("{\n\t.reg .b64 A,B,D;\n\t"
        "mov.b64 A,{%2,%3};\n\t"
        "mov.b64 B,{%4,%5};\n\t"
        "mul.rn.f32x2 D, A, B;\n\t"
        "mov.b64 {%0,%1}, D;\n\t}"
        : "=f"(r.x), "=f"(r.y)
        : "f"(a.x), "f"(a.y), "f"(b.x), "f"(b.y));
    return r;
}

// Mapping: 16 amplitudes/thread (k bits 0..3), 16 lanes/element, elem = lane bit 4.
//   odd qubits  (1,3,5,7) -> LOCAL k bits : q7->k1, q5->k2, q3->k4, q1->k8
//   even qubits (0,2,4,6) -> LANE bits    : q6->l1, q4->l2, q2->l4, q0->l8
template<int Q> struct QM {
    static constexpr bool local = (Q & 1) != 0;
    static constexpr int mask = local ? (1 << ((7 - Q) >> 1)) : (1 << ((6 - Q) >> 1));
};

__device__ __forceinline__ constexpr int cpop(int v){
    return (v&1)+((v>>1)&1)+((v>>2)&1)+((v>>3)&1);
}

__device__ __forceinline__ C2 cmul_s(C2 a, C2 b){
    return mkc(a.x*b.x - a.y*b.y, a.x*b.y + a.y*b.x);
}

// multiply a[k] by i^e(k), e(k) = (popc(k&MP) + 3*popc(k&MM)) & 3   (compile-time per k)
template<int MP, int MM>
__device__ __forceinline__ void kdiag(C2 a[16]){
    #pragma unroll
    for (int k = 0; k < 16; ++k){
        const int e = (cpop(k & MP) + 3 * cpop(k & MM)) & 3;
        if (e == 1){ float t = a[k].x; a[k].x = -a[k].y; a[k].y =  t; }
        else if (e == 2){ a[k].x = -a[k].x; a[k].y = -a[k].y; }
        else if (e == 3){ float t = a[k].x; a[k].x =  a[k].y; a[k].y = -t; }
    }
}

// multiply ALL regs by complex W
__device__ __forceinline__ void diag_all(C2 a[16], C2 W){
    C2 P = DUP(W.x), Q = mkc(-W.y, W.y);
    #pragma unroll
    for (int k = 0; k < 16; ++k)
        a[k] = pfma(Q, mkc(a[k].y, a[k].x), pmul(P, a[k]));
}

// multiply a[k] by w1^popc(k&MASK)   (compile-time exponent per k)
template<int MASK>
__device__ __forceinline__ void zpow(C2 a[16], C2 w1, C2 w2, C2 w3){
    #pragma unroll
    for (int k = 0; k < 16; ++k){
        const int p = cpop(k & MASK);
        if (p){
            C2 w = (p == 1) ? w1 : (p == 2) ? w2 : w3;
            a[k] = pfma(mkc(-w.y, w.y), mkc(a[k].y, a[k].x), pmul(DUP(w.x), a[k]));
        }
    }
}

// local RY on k bit M
template<int M>
__device__ __forceinline__ void ry_localM(C2 a[16], float c, float s){
    C2 c2 = DUP(c), s2 = DUP(s), ns2 = DUP(-s);
    #pragma unroll
    for (int k0 = 0; k0 < 16; ++k0) if (!(k0 & M)){
        int k1 = k0 | M;
        C2 a0 = a[k0], a1 = a[k1];
        a[k0] = pfma(c2, a0, pmul(ns2, a1));
        a[k1] = pfma(s2, a0, pmul(c2, a1));
    }
}

// X on local bit M, conditioned on runtime flag cb
template<int M>
__device__ __forceinline__ void xsel_local(C2 a[16], bool cb){
    #pragma unroll
    for (int k0 = 0; k0 < 16; ++k0) if (!(k0 & M)){
        int k1 = k0 | M;
        C2 t0 = a[k0], t1 = a[k1];
        a[k0] = cb ? t1 : t0;
        a[k1] = cb ? t0 : t1;
    }
}

// merged parity-0 CX stage: a[k] -> shfl_xor(a[k], k)
__device__ __forceinline__ void cx_shfl_id(C2 a[16]){
    #pragma unroll
    for (int k = 1; k < 16; ++k){
        a[k].x = __shfl_xor_sync(FULL, a[k].x, k);
        a[k].y = __shfl_xor_sync(FULL, a[k].y, k);
    }
}

// merged parity-1 conditional-X stage: mask M(k) = (k>>1)&7
__device__ __forceinline__ void cx_shfl_half(C2 a[16]){
    #pragma unroll
    for (int k = 2; k < 16; ++k){
        const int M = (k >> 1) & 7;
        if (M){
            a[k].x = __shfl_xor_sync(FULL, a[k].x, M);
            a[k].y = __shfl_xor_sync(FULL, a[k].y, M);
        }
    }
}

// lane RY on lane bit LM with per-k coefficient select by k&KM.
// ssp/sdp are pre-sign-adjusted: s if (lane&LM) else -s.
template<int LM, int KM>
__device__ __forceinline__ void ry_lane_sel(C2 a[16], float cs, float ssp, float cd, float sdp){
    #pragma unroll
    for (int k = 0; k < 16; ++k){
        const float ce = (k & KM) ? cd : cs;
        const float se = (k & KM) ? sdp : ssp;
        C2 p;
        p.x = __shfl_xor_sync(FULL, a[k].x, LM);
        p.y = __shfl_xor_sync(FULL, a[k].y, LM);
        a[k] = pfma(DUP(ce), a[k], pmul(DUP(se), p));
    }
}

// local RY on bit MT with per-k coeff selected by k&KM, then compile-time X if k&KM
template<int KM, int MT>
__device__ __forceinline__ void ry_local_sel_x(C2 a[16], float cs, float ss, float cd, float sd){
    #pragma unroll
    for (int k0 = 0; k0 < 16; ++k0) if (!(k0 & MT)){
        int k1 = k0 | MT;
        const float ce = (k0 & KM) ? cd : cs;
        const float se = (k0 & KM) ? sd : ss;
        C2 a0 = a[k0], a1 = a[k1];
        C2 n0 = pfma(DUP(ce), a0, pmul(DUP(-se), a1));
        C2 n1 = pfma(DUP(se), a0, pmul(DUP(ce), a1));
        if (k0 & KM){ a[k0] = n1; a[k1] = n0; }
        else        { a[k0] = n0; a[k1] = n1; }
    }
}

// compile-time local CX: control bit MC, target bit MT
template<int MC, int MT>
__device__ __forceinline__ void cx_local(C2 a[16]){
    #pragma unroll
    for (int k0 = 0; k0 < 16; ++k0) if ((k0 & MC) && !(k0 & MT)){
        int k1 = k0 | MT; C2 t = a[k0]; a[k0] = a[k1]; a[k1] = t;
    }
}

// ---------------- generic complex 1q gate (local qubits only here) ----------------
template<int Q>
__device__ __forceinline__ void g1(C2 a[16], C2 u00, C2 u01, C2 u10, C2 u11, int lane){
    constexpr int m = QM<Q>::mask;
    if constexpr (QM<Q>::local) {
        C2 x00 = DUP(u00.x), y00 = mkc(-u00.y, u00.y);
        C2 x01 = DUP(u01.x), y01 = mkc(-u01.y, u01.y);
        C2 x10 = DUP(u10.x), y10 = mkc(-u10.y, u10.y);
        C2 x11 = DUP(u11.x), y11 = mkc(-u11.y, u11.y);
        #pragma unroll
        for (int k0 = 0; k0 < 16; ++k0) if (!(k0 & m)) {
            int k1 = k0 | m;
            C2 a0 = a[k0], a1 = a[k1];
            C2 a0s = mkc(a0.y, a0.x), a1s = mkc(a1.y, a1.x);
            C2 t0 = pmul(x00, a0); t0 = pfma(y00, a0s, t0);
            t0 = pfma(x01, a1, t0); t0 = pfma(y01, a1s, t0);
            C2 t1 = pmul(x10, a0); t1 = pfma(y10, a0s, t1);
            t1 = pfma(x11, a1, t1); t1 = pfma(y11, a1s, t1);
            a[k0] = t0; a[k1] = t1;
        }
    } else {
        bool hi = (lane & m) != 0;
        C2 xA = hi ? DUP(u11.x) : DUP(u00.x);
        C2 yA = hi ? mkc(-u11.y, u11.y) : mkc(-u00.y, u00.y);
        C2 xB = hi ? DUP(u10.x) : DUP(u01.x);
        C2 yB = hi ? mkc(-u10.y, u10.y) : mkc(-u01.y, u01.y);
        #pragma unroll
        for (int k = 0; k < 16; ++k) {
            float px = __shfl_xor_sync(FULL, a[k].x, m);
            float py = __shfl_xor_sync(FULL, a[k].y, m);
            C2 as_ = mkc(a[k].y, a[k].x);
            C2 t = pmul(xA, a[k]); t = pfma(yA, as_, t);
            t = pfma(xB, mkc(px, py), t); t = pfma(yB, mkc(py, px), t);
            a[k] = t;
        }
    }
}

// ---------------- CRX (packed) ----------------
template<int QC, int QT>
__device__ __forceinline__ void gcrx(C2 a[16], float c, float s, int lane){
    constexpr int mc = QM<QC>::mask, mt = QM<QT>::mask;
    if constexpr (QM<QC>::local && QM<QT>::local) {
        C2 c2 = DUP(c), sn = mkc(s, -s);
        #pragma unroll
        for (int k0 = 0; k0 < 16; ++k0) if ((k0 & mc) && !(k0 & mt)) {
            int k1 = k0 | mt;
            C2 a0 = a[k0], a1 = a[k1];
            a[k0] = pfma(c2, a0, pmul(sn, mkc(a1.y, a1.x)));
            a[k1] = pfma(c2, a1, pmul(sn, mkc(a0.y, a0.x)));
        }
    } else if constexpr (QM<QC>::local) { // control local, target lane
        C2 c2 = DUP(c), sn = mkc(s, -s);
        #pragma unroll
        for (int k = 0; k < 16; ++k) if (k & mc) {
            float px = __shfl_xor_sync(FULL, a[k].x, mt);
            float py = __shfl_xor_sync(FULL, a[k].y, mt);
            a[k] = pfma(c2, a[k], pmul(sn, mkc(py, px)));
        }
    } else if constexpr (QM<QT>::local) { // control lane, target local
        bool cb = (lane & mc) != 0;
        C2 c2 = DUP(cb ? c : 1.0f);
        C2 sn = cb ? mkc(s, -s) : mkc(0.f, 0.f);
        #pragma unroll
        for (int k0 = 0; k0 < 16; ++k0) if (!(k0 & mt)) {
            int k1 = k0 | mt;
            C2 a0 = a[k0], a1 = a[k1];
            a[k0] = pfma(c2, a0, pmul(sn, mkc(a1.y, a1.x)));
            a[k1] = pfma(c2, a1, pmul(sn, mkc(a0.y, a0.x)));
        }
    } else {
        bool cb = (lane & mc) != 0;
        C2 c2 = DUP(cb ? c : 1.0f);
        C2 sn = cb ? mkc(s, -s) : mkc(0.f, 0.f);
        #pragma unroll
        for (int k = 0; k < 16; ++k) {
            float px = __shfl_xor_sync(FULL, a[k].x, mt);
            float py = __shfl_xor_sync(FULL, a[k].y, mt);
            a[k] = pfma(c2, a[k], pmul(sn, mkc(py, px)));
        }
    }
}

// ---------------- real-state encode gates ----------------
template<int Q>
__device__ __forceinline__ void gryR(float r[16], float c, float s, int lane){
    constexpr int m = QM<Q>::mask;
    C2 c2 = DUP(c);
    if constexpr (QM<Q>::local) {
        if constexpr (m == 1) {
            C2 snn = mkc(-s, s);
            #pragma unroll
            for (int j = 0; j < 8; ++j) {
                C2 v = mkc(r[2*j], r[2*j+1]);
                C2 res = pfma(snn, mkc(v.y, v.x), pmul(c2, v));
                r[2*j] = res.x; r[2*j+1] = res.y;
            }
        } else {
            constexpr int pm = m >> 1;
            C2 s2 = DUP(s), ns2 = DUP(-s);
            #pragma unroll
            for (int j0 = 0; j0 < 8; ++j0) if (!(j0 & pm)) {
                int j1 = j0 | pm;
                C2 v0 = mkc(r[2*j0], r[2*j0+1]);
                C2 v1 = mkc(r[2*j1], r[2*j1+1]);
                C2 n0 = pfma(c2, v0, pmul(ns2, v1));
                C2 n1 = pfma(s2, v0, pmul(c2, v1));
                r[2*j0] = n0.x; r[2*j0+1] = n0.y;
                r[2*j1] = n1.x; r[2*j1+1] = n1.y;
            }
        }
    } else {
        C2 sg2 = (lane & m) ? DUP(s) : DUP(-s);
        #pragma unroll
        for (int j = 0; j < 8; ++j) {
            float px = __shfl_xor_sync(FULL, r[2*j],   m);
            float py = __shfl_xor_sync(FULL, r[2*j+1], m);
            C2 v = mkc(r[2*j], r[2*j+1]);
            C2 res = pfma(c2, v, pmul(sg2, mkc(px, py)));
            r[2*j] = res.x; r[2*j+1] = res.y;
        }
    }
}

template<int QC, int QT>
__device__ __forceinline__ void gcxR(float r[16], int lane){
    constexpr int mc = QM<QC>::mask, mt = QM<QT>::mask;
    if constexpr (QM<QC>::local && QM<QT>::local) {
        #pragma unroll
        for (int k0 = 0; k0 < 16; ++k0) if ((k0 & mc) && !(k0 & mt)) {
            int k1 = k0 | mt; float t = r[k0]; r[k0] = r[k1]; r[k1] = t;
        }
    } else if constexpr (QM<QC>::local) {
        #pragma unroll
        for (int k = 0; k < 16; ++k) if (k & mc)
            r[k] = __shfl_xor_sync(FULL, r[k], mt);
    } else if constexpr (QM<QT>::local) {
        bool cb = (lane & mc) != 0;
        #pragma unroll
        for (int k0 = 0; k0 < 16; ++k0) if (!(k0 & mt)) {
            int k1 = k0 | mt;
            float t0 = r[k0], t1 = r[k1];
            r[k0] = cb ? t1 : t0;
            r[k1] = cb ? t0 : t1;
        }
    } else {
        bool cb = (lane & mc) != 0;
        #pragma unroll
        for (int k = 0; k < 16; ++k) {
            float pv = __shfl_xor_sync(FULL, r[k], mt);
            r[k] = cb ? pv : r[k];
        }
    }
}

__device__ __forceinline__ float wsum16(float v){
    #pragma unroll
    for (int o = 8; o; o >>= 1) v += __shfl_xor_sync(FULL, v, o);
    return v;
}

__device__ __forceinline__ void u3m(const float* p, C2& U00, C2& U01, C2& U10, C2& U11){
    float t = p[0], ph = p[1], la = p[2];
    float st, ct, sp, cp, sl, cl, spl, cpl;
    __sincosf(t * 0.5f, &st, &ct);
    __sincosf(ph, &sp, &cp);
    __sincosf(la, &sl, &cl);
    __sincosf(ph + la, &spl, &cpl);
    U00 = mkc(ct, 0.f);
    U01 = mkc(-cl*st, -sl*st);
    U10 = mkc( cp*st,  sp*st);
    U11 = mkc(cpl*ct, spl*ct);
}

__global__ void __launch_bounds__(128, 8)
qcnn_kernel(const float* __restrict__ x,
            const float* __restrict__ rz_p,  const float* __restrict__ ry_p,
            const float* __restrict__ ry2_p, const float* __restrict__ crx_p,
            const float* __restrict__ u3_p,  const float* __restrict__ u3b_p,
            const float* __restrict__ W1,    const float* __restrict__ b1,
            const float* __restrict__ W2,    const float* __restrict__ b2,
            float* __restrict__ out, int B)
{
    const int warp = (blockIdx.x * blockDim.x + threadIdx.x) >> 5;
    const int lane = threadIdx.x & 31;
    const int hl   = lane & 15;
    const int elem = warp * 2 + (lane >> 4);
    if (warp * 2 >= B) return;
    const int e = (elem < B) ? elem : (B - 1);

    // ================= encode (state purely REAL) =================
    float2 av = reinterpret_cast<const float2*>(x)[e * 16 + hl];
    float c0, s0, c1, s1;
    __sincosf(0.5f * av.x, &s0, &c0);
    __sincosf(0.5f * av.y, &s1, &c1);

    float r[16];
    #pragma unroll
    for (int k = 0; k < 16; ++k) r[k] = 0.0f;
    r[0] = (hl == 0) ? 1.0f : 0.0f;

    #define RYQ(CY,Q) do { \
        const int idx_ = (CY)*8 + (Q); \
        int src_ = (lane & 16) | (idx_ >> 1); \
        float cc_ = __shfl_sync(FULL, ((idx_ & 1) ? c1 : c0), src_); \
        float ss_ = __shfl_sync(FULL, ((idx_ & 1) ? s1 : s0), src_); \
        gryR<Q>(r, cc_, ss_, lane); } while(0)

    #define ENC_CYC(CY) \
        RYQ(CY,0); RYQ(CY,1); RYQ(CY,2); RYQ(CY,3); \
        RYQ(CY,4); RYQ(CY,5); RYQ(CY,6); RYQ(CY,7); \
        gcxR<0,1>(r,lane); gcxR<1,2>(r,lane); gcxR<2,3>(r,lane); gcxR<3,4>(r,lane); \
        gcxR<4,5>(r,lane); gcxR<5,6>(r,lane); gcxR<6,7>(r,lane); gcxR<7,0>(r,lane);

    ENC_CYC(0) ENC_CYC(1) ENC_CYC(2) ENC_CYC(3)

    // ================= psi1 FIRST (short; r stays live only here) ====
    C2 a[16];
    #pragma unroll
    for (int k = 0; k < 16; ++k) a[k] = mkc(r[k], 0.f);

    {   // layer 0
        float xc, xs;
        __sincosf(crx_p[0] * 0.5f, &xs, &xc);
        gcrx<0,1>(a, xc, xs, lane);
        gcrx<2,3>(a, xc, xs, lane);
        gcrx<4,5>(a, xc, xs, lane);
        gcrx<6,7>(a, xc, xs, lane);
        gcrx<1,2>(a, xc, xs, lane);
        gcrx<3,4>(a, xc, xs, lane);
        gcrx<5,6>(a, xc, xs, lane);
        C2 U00, U01, U10, U11;
        u3m(u3b_p, U00, U01, U10, U11);
        g1<1>(a, U00, U01, U10, U11, lane);
        g1<3>(a, U00, U01, U10, U11, lane);
        g1<5>(a, U00, U01, U10, U11, lane);
        g1<7>(a, U00, U01, U10, U11, lane);
    }
    {   // layer 1
        float xc, xs;
        __sincosf(crx_p[1] * 0.5f, &xs, &xc);
        gcrx<1,3>(a, xc, xs, lane);
        gcrx<5,7>(a, xc, xs, lane);
        gcrx<3,5>(a, xc, xs, lane);
        C2 U00, U01, U10, U11;
        u3m(u3b_p + 3, U00, U01, U10, U11);
        g1<3>(a, U00, U01, U10, U11, lane);
        g1<7>(a, U00, U01, U10, U11, lane);
    }

    float f2, f3;
    {
        float p3 = 0.f, p7 = 0.f;
        #pragma unroll
        for (int k = 0; k < 16; ++k) {
            float m = fmaf(a[k].x, a[k].x, a[k].y * a[k].y);
            p3 += (k & 4) ? -m : m;
            p7 += (k & 1) ? -m : m;
        }
        f2 = wsum16(p3);
        f3 = wsum16(p7);
    }

    // ================= psi0 (restructured with merged stages) =================
    #pragma unroll
    for (int k = 0; k < 16; ++k) a[k] = mkc(r[k], 0.f);

    {   // ---- layer 0 ----
        float zs, zc;
        __sincosf(rz_p[0], &zs, &zc);
        C2 w1 = mkc(zc, zs);
        C2 w2 = cmul_s(w1, w1);
        C2 w3 = cmul_s(w2, w1);
        C2 w4 = cmul_s(w2, w2);
        float yc, ys, y2c, y2s;
        __sincosf(ry_p[0]  * 0.5f, &ys,  &yc);
        __sincosf(ry2_p[0] * 0.5f, &y2s, &y2c);
        const float cs_ = yc*y2c - ys*y2s, ss_ = ys*y2c + yc*y2s;   // theta1+theta2
        const float cd_ = yc*y2c + ys*y2s, sd_ = ys*y2c - yc*y2s;   // theta1-theta2

        // ---- parity-0 sweep: pairs (0,1),(2,3),(4,5),(6,7) ----
        kdiag<0, 15>(a);          // gate-1 x4: (-i)^popc(k)
        cx_shfl_id(a);            // gate-2 x4 merged
        {                         // gate-3 x4 merged: W = w1^popc(hl)
            int p = __popc((unsigned)hl);
            C2 W  = (p & 1) ? w1 : mkc(1.f, 0.f);
            C2 Wb = (p & 2) ? w2 : mkc(1.f, 0.f);
            W = cmul_s(W, Wb);
            W.x = (p & 4) ? w4.x : W.x;
            W.y = (p & 4) ? w4.y : W.y;
            diag_all(a, W);
        }
        {   // gates 4-6 per pair: RY(theta_eff) + conditional X
            bool cb; float ce, se;
            cb = (hl & 8); ce = cb ? cd_ : cs_; se = cb ? sd_ : ss_;
            ry_localM<8>(a, ce, se); xsel_local<8>(a, cb);
            cb = (hl & 4); ce = cb ? cd_ : cs_; se = cb ? sd_ : ss_;
            ry_localM<4>(a, ce, se); xsel_local<4>(a, cb);
            cb = (hl & 2); ce = cb ? cd_ : cs_; se = cb ? sd_ : ss_;
            ry_localM<2>(a, ce, se); xsel_local<2>(a, cb);
            cb = (hl & 1); ce = cb ? cd_ : cs_; se = cb ? sd_ : ss_;
            ry_localM<1>(a, ce, se); xsel_local<1>(a, cb);
        }
        cx_shfl_id(a);            // gate-7 x4 merged
        {   // gate-8 x4 (i^popc(hl)) merged with parity-1 gate-1 x3 ((-i)^popc(hl&7)) = i^bit3(hl)
            bool cb = (hl & 8);
            diag_all(a, cb ? mkc(0.f, 1.f) : mkc(1.f, 0.f));
        }

        // ---- parity-1 sweep: pairs (1,2),(3,4),(5,6) ----
        xsel_local<8>(a, (hl & 4) != 0);   // gate-2: CX(ctrl q2 lane, tgt q1 local)
        xsel_local<4>(a, (hl & 2) != 0);   //         CX(ctrl q4, tgt q3)
        xsel_local<2>(a, (hl & 1) != 0);   //         CX(ctrl q6, tgt q5)
        zpow<14>(a, w1, w2, w3);           // gate-3 x3 merged: w1^popc(k&14)
        {   // gates 4-6: lane RYs with per-k coeff, then merged conditional-X shuffle
            float sp, dp;
            sp = (hl & 4) ? ss_ : -ss_; dp = (hl & 4) ? sd_ : -sd_;
            ry_lane_sel<4, 8>(a, cs_, sp, cd_, dp);
            sp = (hl & 2) ? ss_ : -ss_; dp = (hl & 2) ? sd_ : -sd_;
            ry_lane_sel<2, 4>(a, cs_, sp, cd_, dp);
            sp = (hl & 1) ? ss_ : -ss_; dp = (hl & 1) ? sd_ : -sd_;
            ry_lane_sel<1, 2>(a, cs_, sp, cd_, dp);
            cx_shfl_half(a);               // merged gate-5 X's: mask (k>>1)&7
        }
        xsel_local<8>(a, (hl & 4) != 0);   // gate-7 x3
        xsel_local<4>(a, (hl & 2) != 0);
        xsel_local<2>(a, (hl & 1) != 0);
        kdiag<14, 0>(a);                   // gate-8 x3: i^popc(k&14)

        // U3a on q1,q3,q5,q7
        C2 U00, U01, U10, U11;
        u3m(u3_p, U00, U01, U10, U11);
        g1<1>(a, U00, U01, U10, U11, lane);
        g1<3>(a, U00, U01, U10, U11, lane);
        g1<5>(a, U00, U01, U10, U11, lane);
        g1<7>(a, U00, U01, U10, U11, lane);
    }

    {   // ---- layer 1 (qubits 1,3,5,7 — all local) ----
        float zs, zc;
        __sincosf(rz_p[1], &zs, &zc);
        C2 w1 = mkc(zc, zs);
        C2 w2 = cmul_s(w1, w1);
        float yc, ys, y2c, y2s;
        __sincosf(ry_p[1]  * 0.5f, &ys,  &yc);
        __sincosf(ry2_p[1] * 0.5f, &y2s, &y2c);
        const float cs_ = yc*y2c - ys*y2s, ss_ = ys*y2c + yc*y2s;
        const float cd_ = yc*y2c + ys*y2s, sd_ = ys*y2c - yc*y2s;

        // parity-0: pairs (1,3),(5,7)
        kdiag<0, 5>(a);                     // gate-1: (-i)^popc(k&5)  [q3->k4, q7->k1]
        cx_local<4, 8>(a);                  // gate-2: (1,3) ctrl k4 tgt k8
        cx_local<1, 2>(a);                  //          (5,7) ctrl k1 tgt k2
        zpow<10>(a, w1, w2, w2);            // gate-3: w1^popc(k&10)  [q1->k8, q5->k2], p<=2
        ry_local_sel_x<8, 4>(a, cs_, ss_, cd_, sd_);   // (1,3): ctrl k8, tgt k4
        ry_local_sel_x<2, 1>(a, cs_, ss_, cd_, sd_);   // (5,7): ctrl k2, tgt k1
        cx_local<4, 8>(a);                  // gate-7
        cx_local<1, 2>(a);
        // gate-8 (i^popc(k&10)) merged with parity-1 gate-1 ((-i)^popc(k&2)):
        kdiag<10, 2>(a);

        // parity-1: pair (3,5): qc=3(k4), qt=5(k2)
        cx_local<2, 4>(a);                  // gate-2: ctrl k2 tgt k4
        zpow<4>(a, w1, w2, w2);             // gate-3: w1^[k&4]
        ry_local_sel_x<4, 2>(a, cs_, ss_, cd_, sd_);
        cx_local<2, 4>(a);                  // gate-7
        kdiag<4, 0>(a);                     // gate-8: i^[k&4]

        // U3a layer-1 on q3,q7
        C2 U00, U01, U10, U11;
        u3m(u3_p + 3, U00, U01, U10, U11);
        g1<3>(a, U00, U01, U10, U11, lane);
        g1<7>(a, U00, U01, U10, U11, lane);
    }

    float f0, f1;
    {
        float p3 = 0.f, p7 = 0.f;
        #pragma unroll
        for (int k = 0; k < 16; ++k) {
            float m = fmaf(a[k].x, a[k].x, a[k].y * a[k].y);
            p3 += (k & 4) ? -m : m;
            p7 += (k & 1) ? -m : m;
        }
        f0 = wsum16(p3);
        f1 = wsum16(p7);
    }

    // ================= MLP head =================
    float hv = 0.f;
    if (hl < 15) {
        float z = b1[hl];
        z = fmaf(W1[hl*4+0], f0, z);
        z = fmaf(W1[hl*4+1], f1, z);
        z = fmaf(W1[hl*4+2], f2, z);
        z = fmaf(W1[hl*4+3], f3, z);
        hv = tanhf(z) * W2[hl];
    }
    float s = wsum16(hv);
    if (hl == 0 && elem < B) {
        float zf = s + b2[0];
        out[elem] = 1.0f / (1.0f + __expf(-zf));
    }
}

extern "C" void kernel_launch(void* const* d_in, const int* in_sizes, int n_in,
                              void* d_out, int out_size) {
    const float* x     = (const float*)d_in[0];
    const float* rz_p  = (const float*)d_in[1];
    const float* ry_p  = (const float*)d_in[2];
    const float* ry2_p = (const float*)d_in[3];
    const float* crx_p = (const float*)d_in[4];
    const float* u3_p  = (const float*)d_in[5];
    const float* u3b_p = (const float*)d_in[6];
    const float* W1    = (const float*)d_in[7];
    const float* b1    = (const float*)d_in[8];
    const float* W2    = (const float*)d_in[9];
    const float* b2    = (const float*)d_in[10];

    int B = in_sizes[0] / 32;          // x is (B, 32)
    const int threads = 128;
    int blocks = (B + 7) / 8;
    qcnn_kernel<<<blocks, threads>>>(x, rz_p, ry_p, ry2_p, crx_p, u3_p, u3b_p,
                                     W1, b1, W2, b2, (float*)d_out, B);
}